// round 7
// baseline (speedup 1.0000x reference)
#include <cuda_runtime.h>
#include <stdint.h>

#define NN 100000
#define EE 1600000
#define F_IN 128
#define F_H 64
#define F_OUT 32

// ---------------- device scratch (static allocation only) ----------------
__device__ int   g_is64;
__device__ int   g_cnt[NN];        // in-degree (edges only, excl self-loop)
__device__ int   g_off[NN];        // CSR offsets (exclusive scan of cnt)
__device__ int   g_cur[NN];        // fill cursors
__device__ int   g_bsum[512];      // block sums for scan
__device__ int   g_boff[512];      // block offsets
__device__ int   g_srcs[EE];       // dst-grouped source ids (int32)
__device__ float g_dinv[NN];
__device__ float g_g1[NN * F_H];
__device__ float g_acc1[NN * F_H];
__device__ float g_g2[NN * F_OUT];

// Blackwell packed f32x2 FMA
__device__ __forceinline__ unsigned long long fma2(unsigned long long a,
                                                   unsigned long long b,
                                                   unsigned long long c) {
    unsigned long long d;
    asm("fma.rn.f32x2 %0, %1, %2, %3;" : "=l"(d) : "l"(a), "l"(b), "l"(c));
    return d;
}
union F2U { float2 f; unsigned long long u; };

// ---------------- fused: zero cnt + dtype detection ----------------
__global__ void k_detzero(const unsigned long long* __restrict__ idx, int n) {
    int i = blockIdx.x * blockDim.x + threadIdx.x;
    if (i < n) g_cnt[i] = 0;
    if (blockIdx.x == 0 && threadIdx.x < 32) {
        unsigned mask = __ballot_sync(0xffffffffu,
                                      idx[threadIdx.x] >= (unsigned long long)NN);
        if (threadIdx.x == 0) g_is64 = (mask == 0u) ? 1 : 0;
    }
}

__global__ void k_count(const void* __restrict__ idxp, int E) {
    int e = blockIdx.x * blockDim.x + threadIdx.x;
    if (e >= E) return;
    int dst;
    if (g_is64) dst = (int)((const long long*)idxp)[E + e];
    else        dst = ((const int*)idxp)[E + e];
    atomicAdd(&g_cnt[dst], 1);
}

// ---------------- 3-kernel exclusive scan over g_cnt -> g_off ----------------
__global__ void k_scan1(int n) {
    __shared__ int sh[256];
    int t = threadIdx.x;
    int idx = blockIdx.x * 256 + t;
    int c = (idx < n) ? g_cnt[idx] : 0;
    sh[t] = c;
    __syncthreads();
    #pragma unroll
    for (int o = 1; o < 256; o <<= 1) {
        int x = sh[t];
        int y = (t >= o) ? sh[t - o] : 0;
        __syncthreads();
        sh[t] = x + y;
        __syncthreads();
    }
    int incl = sh[t];
    if (idx < n) g_off[idx] = incl - c;
    if (t == 255) g_bsum[blockIdx.x] = incl;
}

__global__ void k_scan2(int nb) {
    __shared__ int sh[512];
    int t = threadIdx.x;
    int v = (t < nb) ? g_bsum[t] : 0;
    sh[t] = v;
    __syncthreads();
    #pragma unroll
    for (int o = 1; o < 512; o <<= 1) {
        int x = sh[t];
        int y = (t >= o) ? sh[t - o] : 0;
        __syncthreads();
        sh[t] = x + y;
        __syncthreads();
    }
    if (t < nb) g_boff[t] = sh[t] - v;
}

__global__ void k_scan3(int n) {
    int i = blockIdx.x * blockDim.x + threadIdx.x;
    if (i >= n) return;
    int off = g_off[i] + g_boff[i >> 8];
    g_off[i] = off;
    g_cur[i] = off;
    g_dinv[i] = rsqrtf((float)(g_cnt[i] + 1));   // +1 self-loop
}

// ---------------- FAT kernel: gemm1 blocks + CSR-fill blocks ----------------
// gemm: g1[i][j] = dinv[i] * dot(x[i,:], W1[j,:]).  64 rows/block,
// 8 warps x 8 rows, f32x2 FMAs, k4-stepped loads (x via LDS.128 broadcast).
// fill: blocks >= gemmBlocks scatter src ids into dst-grouped g_srcs.
__global__ void __launch_bounds__(256) k_gemm_fill(const float* __restrict__ x,
                                                   const float* __restrict__ W1, int n,
                                                   const void* __restrict__ idxp, int E,
                                                   int gemmBlocks) {
    __shared__ float2 W1p[64 * 64];     // [k2][j]  32KB
    __shared__ float  xs[64][F_IN];     // 32KB

    if (blockIdx.x >= gemmBlocks) {
        // ---- fill path ----
        int e = (blockIdx.x - gemmBlocks) * 256 + threadIdx.x;
        if (e < E) {
            int src, dst;
            if (g_is64) {
                const long long* I = (const long long*)idxp;
                src = (int)I[e]; dst = (int)I[E + e];
            } else {
                const int* I = (const int*)idxp;
                src = I[e]; dst = I[E + e];
            }
            int pos = atomicAdd(&g_cur[dst], 1);
            g_srcs[pos] = src;
        }
        return;
    }

    // ---- gemm path ----
    int tid = threadIdx.x;
    for (int e = tid; e < 64 * 64; e += 256) {
        int k2 = e >> 6, j = e & 63;
        W1p[e] = *(const float2*)(W1 + j * F_IN + 2 * k2);
    }
    int blockRow = blockIdx.x * 64;
    for (int t = tid; t < 64 * 32; t += 256) {
        int r = t >> 5, s = t & 31;
        if (blockRow + r < n)
            ((float4*)xs[r])[s] = ((const float4*)(x + (size_t)(blockRow + r) * F_IN))[s];
    }
    __syncthreads();

    int w = tid >> 5, lane = tid & 31;
    int r0 = w * 8;
    unsigned long long acc[8][2];
    #pragma unroll
    for (int r = 0; r < 8; r++) { acc[r][0] = 0ull; acc[r][1] = 0ull; }

    #pragma unroll 2
    for (int k4 = 0; k4 < 32; k4++) {
        // two k2-pairs of W for this lane's two columns
        float4 wa = *(const float4*)(W1p + (2 * k4 + 0) * 64 + 2 * lane);
        float4 wb = *(const float4*)(W1p + (2 * k4 + 1) * 64 + 2 * lane);
        F2U wa0, wa1, wb0, wb1;
        wa0.f = make_float2(wa.x, wa.y);  wa1.f = make_float2(wa.z, wa.w);
        wb0.f = make_float2(wb.x, wb.y);  wb1.f = make_float2(wb.z, wb.w);
        #pragma unroll
        for (int r = 0; r < 8; r++) {
            float4 xv = *(const float4*)(xs[r0 + r] + 4 * k4);   // LDS.128 broadcast
            F2U xlo, xhi;
            xlo.f = make_float2(xv.x, xv.y);
            xhi.f = make_float2(xv.z, xv.w);
            acc[r][0] = fma2(xlo.u, wa0.u, acc[r][0]);
            acc[r][1] = fma2(xlo.u, wa1.u, acc[r][1]);
            acc[r][0] = fma2(xhi.u, wb0.u, acc[r][0]);
            acc[r][1] = fma2(xhi.u, wb1.u, acc[r][1]);
        }
    }
    #pragma unroll
    for (int r = 0; r < 8; r++) {
        int row = blockRow + r0 + r;
        if (row < n) {
            float di = rsqrtf((float)(g_cnt[row] + 1));
            F2U a0, a1;
            a0.u = acc[r][0]; a1.u = acc[r][1];
            float v0 = (a0.f.x + a0.f.y) * di;
            float v1 = (a1.f.x + a1.f.y) * di;
            *(float2*)(g_g1 + (size_t)row * F_H + 2 * lane) = make_float2(v0, v1);
        }
    }
}

// ---------------- gather-reduce layer 1: warp per dst node, unroll 8 ----------------
__global__ void __launch_bounds__(256) k_agg1(int n) {
    int tid = threadIdx.x;
    int w = tid >> 5, lane = tid & 31;
    int i = blockIdx.x * 8 + w;
    if (i >= n) return;
    int start = g_off[i];
    int len = g_cnt[i];
    float2 acc = *(const float2*)(g_g1 + (size_t)i * F_H + 2 * lane);  // self-loop
    for (int base = 0; base < len; base += 32) {
        int m = min(32, len - base);
        int s = (lane < m) ? __ldg(&g_srcs[start + base + lane]) : 0;
        int k = 0;
        for (; k + 8 <= m; k += 8) {
            int ss[8];
            #pragma unroll
            for (int u = 0; u < 8; u++) ss[u] = __shfl_sync(0xffffffffu, s, k + u);
            float2 v[8];
            #pragma unroll
            for (int u = 0; u < 8; u++)
                v[u] = *(const float2*)(g_g1 + (size_t)ss[u] * F_H + 2 * lane);
            #pragma unroll
            for (int u = 0; u < 8; u++) { acc.x += v[u].x; acc.y += v[u].y; }
        }
        for (; k < m; k++) {
            int sk = __shfl_sync(0xffffffffu, s, k);
            float2 v = *(const float2*)(g_g1 + (size_t)sk * F_H + 2 * lane);
            acc.x += v.x; acc.y += v.y;
        }
    }
    *(float2*)(g_acc1 + (size_t)i * F_H + 2 * lane) = acc;
}

// ---------------- fused: finalize1 + ReLU + GEMM2 (4 rows/warp) ----------------
__global__ void __launch_bounds__(256) k_fuse2(const float* __restrict__ b1,
                                               const float* __restrict__ W2, int n) {
    __shared__ float W2t[F_H * F_OUT];  // [j][m]  8KB
    __shared__ float rs[32][F_H];       // 8KB
    int tid = threadIdx.x;
    for (int t = tid; t < F_H * F_OUT; t += 256) {
        int m = t / F_H, j = t % F_H;
        W2t[j * F_OUT + m] = W2[t];
    }
    int blockRow = blockIdx.x * 32;
    for (int t = tid; t < 32 * F_H; t += 256) {
        int r = t >> 6, j = t & 63;
        int row = blockRow + r;
        if (row < n) {
            float di = g_dinv[row];
            rs[r][j] = fmaxf(di * g_acc1[(size_t)row * F_H + j] + b1[j], 0.f);
        }
    }
    __syncthreads();

    int w = tid >> 5, lane = tid & 31;
    int r0 = w * 4;
    float acc[4] = {0.f, 0.f, 0.f, 0.f};
    #pragma unroll 8
    for (int j = 0; j < F_H; j++) {
        float wv = W2t[j * F_OUT + lane];
        #pragma unroll
        for (int r = 0; r < 4; r++) acc[r] += rs[r0 + r][j] * wv;
    }
    #pragma unroll
    for (int r = 0; r < 4; r++) {
        int row = blockRow + r0 + r;
        if (row < n)
            g_g2[(size_t)row * F_OUT + lane] = acc[r] * g_dinv[row];
    }
}

// ---------------- gather-reduce layer 2 + epilogue -> out, unroll 8 ----------------
__global__ void __launch_bounds__(256) k_agg2(const float* __restrict__ b2,
                                              float* __restrict__ out, int n) {
    int tid = threadIdx.x;
    int w = tid >> 5, lane = tid & 31;
    int i = blockIdx.x * 8 + w;
    if (i >= n) return;
    int start = g_off[i];
    int len = g_cnt[i];
    float acc = g_g2[(size_t)i * F_OUT + lane];   // self-loop
    for (int base = 0; base < len; base += 32) {
        int m = min(32, len - base);
        int s = (lane < m) ? __ldg(&g_srcs[start + base + lane]) : 0;
        int k = 0;
        for (; k + 8 <= m; k += 8) {
            int ss[8];
            #pragma unroll
            for (int u = 0; u < 8; u++) ss[u] = __shfl_sync(0xffffffffu, s, k + u);
            float v[8];
            #pragma unroll
            for (int u = 0; u < 8; u++) v[u] = g_g2[(size_t)ss[u] * F_OUT + lane];
            #pragma unroll
            for (int u = 0; u < 8; u++) acc += v[u];
        }
        for (; k < m; k++) {
            int sk = __shfl_sync(0xffffffffu, s, k);
            acc += g_g2[(size_t)sk * F_OUT + lane];
        }
    }
    out[(size_t)i * F_OUT + lane] = g_dinv[i] * acc + b2[lane];
}

// ---------------- launch ----------------
extern "C" void kernel_launch(void* const* d_in, const int* in_sizes, int n_in,
                              void* d_out, int out_size) {
    const float* x  = (const float*)d_in[0];
    const void*  ei = d_in[1];
    const float* W1 = (const float*)d_in[2];
    const float* b1 = (const float*)d_in[3];
    const float* W2 = (const float*)d_in[4];
    const float* b2 = (const float*)d_in[5];
    float* out = (float*)d_out;

    int N = in_sizes[0] / F_IN;       // 100000
    int E = in_sizes[1] / 2;          // 1600000
    if (N > NN) N = NN;
    if (E > EE) E = EE;

    int nB = (N + 255) / 256;         // 391
    int eB = (E + 255) / 256;         // 6250
    int gemmBlocks = (N + 63) / 64;   // 1563
    int tileBlocks = (N + 31) / 32;   // 3125
    int aggBlocks  = (N + 7) / 8;     // 12500

    k_detzero<<<nB, 256>>>((const unsigned long long*)ei, N);        // 0
    k_count<<<eB, 256>>>(ei, E);                                     // 1
    k_scan1<<<nB, 256>>>(N);                                         // 2
    k_scan2<<<1, 512>>>(nB);                                         // 3
    k_scan3<<<nB, 256>>>(N);                                         // 4
    k_gemm_fill<<<gemmBlocks + eB, 256>>>(x, W1, N, ei, E, gemmBlocks); // 5
    k_agg1<<<aggBlocks, 256>>>(N);                                   // 6
    k_fuse2<<<tileBlocks, 256>>>(b1, W2, N);                         // 7
    k_agg2<<<aggBlocks, 256>>>(b2, out, N);                          // 8
}